// round 4
// baseline (speedup 1.0000x reference)
#include <cuda_runtime.h>

#define BB 4
#define NPTS 2048
#define HH 128
#define WW 128
#define SPLITS 32
#define KCH (NPTS / SPLITS)   // 64 atoms per block
#define CHUNK 32              // atoms resident in shared at once
#define IMG (BB * HH * WW)    // 65536
#define IMG4 (IMG / 4)        // 16384

// Split-K partials: 32 * 64KB = 8 MB (no allocations allowed)
__device__ float g_part[SPLITS * BB * HH * WW];

#define FMA2(acc, a, b) \
    asm("fma.rn.f32x2 %0, %1, %2, %0;" : "+l"(acc) : "l"(a), "l"(b))

union U64F2 { unsigned long long u; float2 f; };

// ---------------------------------------------------------------------------
// Fused kernel: factor tiles in shared (truncated Gaussians, projections
// recomputed warp-uniformly -- no staging arrays), then rank-CHUNK updates
// with packed f32x2 FMAs. Static shared = 48KB exactly.
// ---------------------------------------------------------------------------
__global__ void __launch_bounds__(256) fused_kernel(const float* __restrict__ x,
                                                    const float* __restrict__ rot) {
    int s = blockIdx.x;
    int b = blockIdx.y;

    __shared__ unsigned long long sfy2[CHUNK][128];  // fy duplicated (v,v) - 32KB
    __shared__ float sfx[CHUNK][128];                // 16KB

    int tid = threadIdx.x;
    int tx = tid & 15;
    int ty = tid >> 4;

    const float* R = rot + b * 9;
    float R0 = R[0], R1 = R[1], R2 = R[2];
    float R3 = R[3], R4 = R[4], R5 = R[5];

    unsigned long long acc[8][4];
#pragma unroll
    for (int i = 0; i < 8; i++)
#pragma unroll
        for (int j = 0; j < 4; j++) acc[i][j] = 0ULL;

    int atom_base = b * NPTS + s * KCH;

    for (int c = 0; c < KCH / CHUNK; c++) {
        // --- Phase B: factor tables. e = tid + i*256 -> atom a = e>>7 is
        //     warp-uniform, so each lane recomputes the projection from
        //     broadcast loads (no shared staging, no extra sync).
        const float cexp = -0.22222222f;  // -1/(2*1.5^2)
#pragma unroll 4
        for (int i = 0; i < 16; i++) {
            int e = tid + i * 256;
            int a = e >> 7;
            int p = e & 127;
            const float* xp = x + (atom_base + c * CHUNK + a) * 3;
            float x0 = xp[0], x1 = xp[1], x2 = xp[2];
            const float scale = 51.2f;
            float px = fmaf(R0, x0, fmaf(R1, x1, R2 * x2)) * scale + 64.0f;
            float py = fmaf(R3, x0, fmaf(R4, x1, R5 * x2)) * scale + 64.0f;
            float fp = (float)p;
            float dx = fp - px;
            float dy = fp - py;
            float qx = dx * dx;
            float qy = dy * dy;
            float fx  = (qx < 144.0f) ? __expf(qx * cexp) : 0.0f;
            float fyv = (qy < 144.0f) ? __expf(qy * cexp) : 0.0f;
            sfx[a][p] = fx;
            unsigned int ybits = __float_as_uint(fyv);
            sfy2[a][p] = ((unsigned long long)ybits << 32) | ybits;
        }
        __syncthreads();

        // --- Phase C: rank-CHUNK update, f32x2 packed FMAs ---
#pragma unroll 4
        for (int kk = 0; kk < CHUNK; kk++) {
            unsigned long long yv[8];
#pragma unroll
            for (int i = 0; i < 4; i++) {
                yv[i]     = sfy2[kk][ty * 4 + i];        // broadcast LDS.64
                yv[i + 4] = sfy2[kk][64 + ty * 4 + i];
            }
            float4 xa = *(float4*)&sfx[kk][tx * 4];
            float4 xb = *(float4*)&sfx[kk][64 + tx * 4];
            unsigned long long xp[4];
            asm("mov.b64 %0, {%1, %2};" : "=l"(xp[0]) : "f"(xa.x), "f"(xa.y));
            asm("mov.b64 %0, {%1, %2};" : "=l"(xp[1]) : "f"(xa.z), "f"(xa.w));
            asm("mov.b64 %0, {%1, %2};" : "=l"(xp[2]) : "f"(xb.x), "f"(xb.y));
            asm("mov.b64 %0, {%1, %2};" : "=l"(xp[3]) : "f"(xb.z), "f"(xb.w));
#pragma unroll
            for (int i = 0; i < 8; i++)
#pragma unroll
                for (int j = 0; j < 4; j++)
                    FMA2(acc[i][j], yv[i], xp[j]);
        }
        __syncthreads();
    }

    float* out = g_part + (s * BB + b) * (HH * WW);
#pragma unroll
    for (int i = 0; i < 8; i++) {
        int h = (i < 4) ? (ty * 4 + i) : (64 + ty * 4 + (i - 4));
#pragma unroll
        for (int jj = 0; jj < 2; jj++) {
            int w = (jj == 0) ? (tx * 4) : (64 + tx * 4);
            U64F2 lo, hi;
            lo.u = acc[i][jj * 2];
            hi.u = acc[i][jj * 2 + 1];
            float4 v = make_float4(lo.f.x, lo.f.y, hi.f.x, hi.f.y);
            *(float4*)&out[h * WW + w] = v;
        }
    }
}

// ---------------------------------------------------------------------------
// Combine: 128 blocks, 2 threads per output float4 (16 splits each, 8-deep
// MLP batches), shared-memory merge, then noisy/clean/rot stores.
// ---------------------------------------------------------------------------
__global__ void __launch_bounds__(256) combine_kernel(const float* __restrict__ noise,
                                                      const float* __restrict__ rot,
                                                      float* __restrict__ out) {
    __shared__ float4 buf[128];
    int tid = threadIdx.x;
    int o = blockIdx.x * 128 + (tid >> 1);   // output float4 index, < IMG4
    int half = tid & 1;

    const float4* p = (const float4*)g_part + (half * 16) * IMG4 + o;
    float4 s = make_float4(0.f, 0.f, 0.f, 0.f);
#pragma unroll
    for (int g = 0; g < 2; g++) {
        float4 v[8];
#pragma unroll
        for (int j = 0; j < 8; j++) v[j] = p[(g * 8 + j) * IMG4];
#pragma unroll
        for (int j = 0; j < 8; j++) {
            s.x += v[j].x; s.y += v[j].y; s.z += v[j].z; s.w += v[j].w;
        }
    }
    if (half) buf[tid >> 1] = s;
    __syncthreads();
    if (!half) {
        float4 t = buf[tid >> 1];
        s.x += t.x; s.y += t.y; s.z += t.z; s.w += t.w;
        float4 nz = ((const float4*)noise)[o];
        float4 noisy = make_float4(fmaf(nz.x, 0.1f, s.x), fmaf(nz.y, 0.1f, s.y),
                                   fmaf(nz.z, 0.1f, s.z), fmaf(nz.w, 0.1f, s.w));
        ((float4*)out)[o] = noisy;                 // noisy
        *(float4*)&out[IMG + 36 + o * 4] = s;      // clean (65572 % 4 == 0)
    }
    if (blockIdx.x == 0 && tid < 36) out[IMG + tid] = rot[tid];
}

// ---------------------------------------------------------------------------
extern "C" void kernel_launch(void* const* d_in, const int* in_sizes, int n_in,
                              void* d_out, int out_size) {
    const float* x     = (const float*)d_in[0];  // (4,2048,3)
    const float* rot   = (const float*)d_in[1];  // (4,3,3)
    const float* noise = (const float*)d_in[2];  // (4,128,128)
    float* out = (float*)d_out;

    dim3 grid(SPLITS, BB);
    fused_kernel<<<grid, 256>>>(x, rot);

    combine_kernel<<<IMG4 / 128, 256>>>(noise, rot, out);
}

// round 5
// speedup vs baseline: 1.3257x; 1.3257x over previous
#include <cuda_runtime.h>

#define BB 4
#define NPTS 2048
#define HH 128
#define WW 128
#define SPLITS 32
#define KCH (NPTS / SPLITS)   // 64 atoms per block
#define CHUNK 32              // atoms resident in shared at once
#define IMG (BB * HH * WW)    // 65536
#define IMG4 (IMG / 4)        // 16384

// Split-K partials: 32 * 64KB = 8 MB (no device allocations allowed)
__device__ float g_part[SPLITS * BB * HH * WW];

// ---------------------------------------------------------------------------
// Fused kernel. Warp w owns output rows [16w, 16w+16). Phase A projects the
// chunk's 32 atoms and ballots per-window atom bitmaps; Phase C iterates only
// atoms whose y-support intersects the warp's window (exact: skipped atoms
// have fy==0 on all of the warp's rows).
// ---------------------------------------------------------------------------
__global__ void __launch_bounds__(256) fused_kernel(const float* __restrict__ x,
                                                    const float* __restrict__ rot) {
    int s = blockIdx.x;
    int b = blockIdx.y;

    __shared__ float sfy[CHUNK][128];     // 16KB
    __shared__ float sfx[CHUNK][128];     // 16KB
    __shared__ float spx[CHUNK];
    __shared__ float spy[CHUNK];
    __shared__ unsigned swm[8];           // per-window atom bitmap

    int tid  = threadIdx.x;
    int w    = tid >> 5;        // warp id = row-window id (0..7)
    int lane = tid & 31;
    int rg   = lane >> 4;       // row sub-group (0/1): rows 16w+8rg .. +8
    int cx   = lane & 15;       // column group

    const float* R = rot + b * 9;
    float R0 = R[0], R1 = R[1], R2 = R[2];
    float R3 = R[3], R4 = R[4], R5 = R[5];

    float acc[8][8];
#pragma unroll
    for (int i = 0; i < 8; i++)
#pragma unroll
        for (int j = 0; j < 8; j++) acc[i][j] = 0.0f;

    int atom_base = b * NPTS + s * KCH;

    for (int c = 0; c < KCH / CHUNK; c++) {
        // --- Phase A: warp 0 projects 32 atoms, builds window bitmaps ---
        if (tid < 32) {
            const float* xp = x + (atom_base + c * CHUNK + tid) * 3;
            float x0 = xp[0], x1 = xp[1], x2 = xp[2];
            const float scale = 51.2f;
            float px = fmaf(R0, x0, fmaf(R1, x1, R2 * x2)) * scale + 64.0f;
            float py = fmaf(R3, x0, fmaf(R4, x1, R5 * x2)) * scale + 64.0f;
            spx[tid] = px;
            spy[tid] = py;
            // y-support [py-12, py+12]; window ww covers rows [16ww,16ww+16)
            int w0 = (int)floorf((py - 12.0f) * 0.0625f);
            int w1 = (int)floorf((py + 12.0f) * 0.0625f);
            if (w0 < 0) w0 = 0;
            if (w1 > 7) w1 = 7;
#pragma unroll
            for (int ww = 0; ww < 8; ww++) {
                unsigned bm = __ballot_sync(0xffffffffu, ww >= w0 && ww <= w1);
                if (tid == ww) swm[ww] = bm;
            }
        }
        __syncthreads();

        // --- Phase B: factor tables (cutoff d^2>=144 -> exp ~ 1e-14) ---
        const float cexp = -0.22222222f;  // -1/(2*1.5^2)
#pragma unroll 4
        for (int i = 0; i < 16; i++) {
            int e = tid + i * 256;
            int a = e >> 7;
            int p = e & 127;
            float fp = (float)p;
            float dx = fp - spx[a];
            float dy = fp - spy[a];
            float qx = dx * dx;
            float qy = dy * dy;
            sfx[a][p] = (qx < 144.0f) ? __expf(qx * cexp) : 0.0f;
            sfy[a][p] = (qy < 144.0f) ? __expf(qy * cexp) : 0.0f;
        }
        __syncthreads();

        // --- Phase C: sparse rank update (only atoms hitting this window) ---
        unsigned m = swm[w];
        while (m) {
            int kk = __ffs(m) - 1;
            m &= m - 1;
            float yv[8], xv[8];
            *(float4*)&yv[0] = *(float4*)&sfy[kk][16 * w + 8 * rg];
            *(float4*)&yv[4] = *(float4*)&sfy[kk][16 * w + 8 * rg + 4];
            *(float4*)&xv[0] = *(float4*)&sfx[kk][cx * 4];
            *(float4*)&xv[4] = *(float4*)&sfx[kk][64 + cx * 4];
#pragma unroll
            for (int i = 0; i < 8; i++)
#pragma unroll
                for (int j = 0; j < 8; j++)
                    acc[i][j] = fmaf(yv[i], xv[j], acc[i][j]);
        }
        __syncthreads();   // protect shared before next chunk overwrites
    }

    float* out = g_part + (s * BB + b) * (HH * WW);
#pragma unroll
    for (int i = 0; i < 8; i++) {
        int h = 16 * w + 8 * rg + i;
#pragma unroll
        for (int jj = 0; jj < 2; jj++) {
            int wc = (jj == 0) ? (cx * 4) : (64 + cx * 4);
            float4 v = make_float4(acc[i][jj * 4 + 0], acc[i][jj * 4 + 1],
                                   acc[i][jj * 4 + 2], acc[i][jj * 4 + 3]);
            *(float4*)&out[h * WW + wc] = v;
        }
    }
}

// ---------------------------------------------------------------------------
// Combine: 8 threads per output float4 (4 splits each), butterfly-shuffle
// reduction, 512 blocks for latency coverage.
// ---------------------------------------------------------------------------
__global__ void __launch_bounds__(256) combine_kernel(const float* __restrict__ noise,
                                                      const float* __restrict__ rot,
                                                      float* __restrict__ out) {
    int tid  = threadIdx.x;
    int lane = tid & 31;
    int wp   = tid >> 5;
    int o = blockIdx.x * 32 + wp * 4 + (lane & 3);   // output float4 idx
    int g = lane >> 2;                               // split group 0..7

    const float4* p = (const float4*)g_part;
    float4 v0 = p[(g * 4 + 0) * IMG4 + o];
    float4 v1 = p[(g * 4 + 1) * IMG4 + o];
    float4 v2 = p[(g * 4 + 2) * IMG4 + o];
    float4 v3 = p[(g * 4 + 3) * IMG4 + o];
    float4 s;
    s.x = (v0.x + v1.x) + (v2.x + v3.x);
    s.y = (v0.y + v1.y) + (v2.y + v3.y);
    s.z = (v0.z + v1.z) + (v2.z + v3.z);
    s.w = (v0.w + v1.w) + (v2.w + v3.w);

#pragma unroll
    for (int off = 4; off <= 16; off <<= 1) {
        s.x += __shfl_xor_sync(0xffffffffu, s.x, off);
        s.y += __shfl_xor_sync(0xffffffffu, s.y, off);
        s.z += __shfl_xor_sync(0xffffffffu, s.z, off);
        s.w += __shfl_xor_sync(0xffffffffu, s.w, off);
    }

    if (g == 0) {
        float4 nz = ((const float4*)noise)[o];
        float4 noisy = make_float4(fmaf(nz.x, 0.1f, s.x), fmaf(nz.y, 0.1f, s.y),
                                   fmaf(nz.z, 0.1f, s.z), fmaf(nz.w, 0.1f, s.w));
        ((float4*)out)[o] = noisy;                 // noisy
        *(float4*)&out[IMG + 36 + o * 4] = s;      // clean (65572 % 4 == 0)
    }
    if (blockIdx.x == 0 && tid < 36) out[IMG + tid] = rot[tid];
}

// ---------------------------------------------------------------------------
extern "C" void kernel_launch(void* const* d_in, const int* in_sizes, int n_in,
                              void* d_out, int out_size) {
    const float* x     = (const float*)d_in[0];  // (4,2048,3)
    const float* rot   = (const float*)d_in[1];  // (4,3,3)
    const float* noise = (const float*)d_in[2];  // (4,128,128)
    float* out = (float*)d_out;

    dim3 grid(SPLITS, BB);
    fused_kernel<<<grid, 256>>>(x, rot);

    combine_kernel<<<IMG4 / 32, 256>>>(noise, rot, out);
}